// round 16
// baseline (speedup 1.0000x reference)
#include <cuda_runtime.h>
#include <cuda_fp16.h>
#include <cstdint>

#define BATCH 4
#define SEQ   2048
#define DIM   1024

// ---- scratch (alloc-free rule: __device__ globals) ----
__device__ __half g_x16  [(size_t)BATCH * SEQ * DIM];       // x -> half
__device__ __half g_qkv  [(size_t)BATCH * SEQ * 3 * DIM];   // [8192][3072] half
__device__ float  g_scores[(size_t)BATCH * SEQ * SEQ];      // [4][2048][2048] fp32
__device__ __half g_probs[(size_t)BATCH * SEQ * SEQ];       // softmax(scores) half
__device__ __half g_attn [(size_t)BATCH * SEQ * DIM];       // [8192][1024] half
__device__ __half g_wqkvT[(size_t)3 * DIM * DIM];           // [3072][1024] half
__device__ __half g_woutT[(size_t)DIM * DIM];               // [1024][1024] half
__device__ __half g_vT   [(size_t)BATCH * DIM * SEQ];       // [4][1024][2048] half

// =========================== PTX helpers ===========================
__device__ __forceinline__ void mma_f16(float* d, const uint32_t* a, const uint32_t* b) {
    asm volatile(
        "mma.sync.aligned.m16n8k16.row.col.f32.f16.f16.f32 "
        "{%0,%1,%2,%3}, {%4,%5,%6,%7}, {%8,%9}, {%0,%1,%2,%3};"
        : "+f"(d[0]), "+f"(d[1]), "+f"(d[2]), "+f"(d[3])
        : "r"(a[0]), "r"(a[1]), "r"(a[2]), "r"(a[3]), "r"(b[0]), "r"(b[1]));
}

__device__ __forceinline__ void ldsm_x4(uint32_t* r, uint32_t addr) {
    asm volatile("ldmatrix.sync.aligned.m8n8.x4.shared.b16 {%0,%1,%2,%3}, [%4];"
        : "=r"(r[0]), "=r"(r[1]), "=r"(r[2]), "=r"(r[3]) : "r"(addr));
}

__device__ __forceinline__ uint32_t smem_u32(const void* p) {
    uint32_t a;
    asm("{ .reg .u64 t; cvta.to.shared.u64 t, %1; cvt.u32.u64 %0, t; }"
        : "=r"(a) : "l"(p));
    return a;
}

#define CP_ASYNC16(dst_u32, src_ptr) \
    asm volatile("cp.async.cg.shared.global [%0], [%1], 16;" \
                 :: "r"(dst_u32), "l"(src_ptr) : "memory")
#define CP_COMMIT() asm volatile("cp.async.commit_group;" ::: "memory")
#define CP_WAIT(n)  asm volatile("cp.async.wait_group %0;" :: "n"(n) : "memory")

// ====== GEMM: 128 threads, CTA 128x128, BK=32, warp 64x64 (2x2), 4-stage, frag double-buffer ====
// (R11/R13/R14 core, measured best.)
// C[M,N] = A[M,K] * B[N,K]^T.  A, B half, K contiguous.
// MODE 0: +bias[n]   MODE 1: *scale then mask==0 -> 1e-10   MODE 2: plain
// OUTH: write C as half; else fp32.
// Race-safety: a cp.async group is committed EVERY mainloop iteration (empty near the
// tail), so wait_group 2 always guarantees the consumed stage has landed.
// MODE 1 extra: L2-prefetch the CTA's mask tile during the last K-chunks so the
// epilogue's mask loads hit L2 instead of cold DRAM (pure hint, no semantic change).

constexpr int BM = 128, BN = 128, BK = 32;
constexpr int ROW_HALFS = 40;                          // 32 data + 8 pad, 80 B pitch
constexpr int ROW_BYTES = ROW_HALFS * 2;               // 80
constexpr int A_HALFS = BM * ROW_HALFS;                // 5120
constexpr int STAGE_HALFS = 2 * A_HALFS;               // 10240
constexpr int STAGE_BYTES = STAGE_HALFS * 2;           // 20480
constexpr int NSTAGE = 4;
constexpr int SMEM_BYTES = NSTAGE * STAGE_BYTES;       // 81920

template <int MODE, bool OUTH>
__global__ __launch_bounds__(128, 2) void gemm_f16k(
    const __half* __restrict__ A, int lda,
    const __half* __restrict__ B, int ldb,
    void* __restrict__ Cv, int ldc, int K,
    const float* __restrict__ bias,
    const int* __restrict__ mask, float scale,
    long sA, long sB, long sC, long sM)
{
    extern __shared__ __half smem[];
    const uint32_t smem_base = smem_u32(smem);
    const int tid  = threadIdx.x;
    const int lane = tid & 31;
    const int wid  = tid >> 5;      // 0..3
    const int bz   = blockIdx.z;

    A += (long)bz * sA;
    B += (long)bz * sB;
    if (MODE == 1) mask += (long)bz * sM;

    const int m0 = blockIdx.y * BM;
    const int n0 = blockIdx.x * BN;

    const int wm = (wid & 1) * 64;     // 2 warps in m
    const int wn = (wid >> 1) * 64;    // 2 warps in n

    // ldmatrix per-lane byte offsets (layout verified in R6-R14)
    const uint32_t a_lane = (uint32_t)((lane & 15) * ROW_BYTES + (lane >> 4) * 16);
    const uint32_t b_lane = (uint32_t)(((lane & 7) + ((lane >> 4) << 3)) * ROW_BYTES
                                       + ((lane >> 3) & 1) * 16);

    const uint32_t a_warp = smem_base + (uint32_t)(wm * ROW_BYTES) + a_lane;
    const uint32_t b_warp = smem_base + (uint32_t)(A_HALFS * 2 + wn * ROW_BYTES) + b_lane;

    // cp.async coords: 128 threads; row = tid>>2 (0..31, x4 strides of 32), chunk=(tid&3)*16B
    const int lrow = tid >> 2;
    const int lq   = (tid & 3) * 8;    // halfs

    const __half* Aped = A + (size_t)(m0 + lrow) * lda + lq;
    const __half* Bped = B + (size_t)(n0 + lrow) * ldb + lq;
    const uint32_t a_dst0 = smem_base + (uint32_t)(lrow * ROW_BYTES + lq * 2);
    const uint32_t b_dst0 = smem_base + (uint32_t)(A_HALFS * 2 + lrow * ROW_BYTES + lq * 2);

    const int NITER = K / BK;

    auto issue_stage = [&](int stage, int kc) {
        const uint32_t so = (uint32_t)(stage * STAGE_BYTES);
        const int kb = kc * BK;
        #pragma unroll
        for (int i = 0; i < 4; i++)
            CP_ASYNC16(a_dst0 + so + (uint32_t)(i * 32 * ROW_BYTES),
                       Aped + (size_t)(i * 32) * lda + kb);
        #pragma unroll
        for (int i = 0; i < 4; i++)
            CP_ASYNC16(b_dst0 + so + (uint32_t)(i * 32 * ROW_BYTES),
                       Bped + (size_t)(i * 32) * ldb + kb);
    };

    float acc[4][8][4];
    #pragma unroll
    for (int i = 0; i < 4; i++)
        #pragma unroll
        for (int j = 0; j < 8; j++)
            #pragma unroll
            for (int q = 0; q < 4; q++) acc[i][j][q] = 0.f;

    issue_stage(0, 0); CP_COMMIT();
    issue_stage(1, 1); CP_COMMIT();
    issue_stage(2, 2); CP_COMMIT();

    uint32_t afr[2][4][4], bfr[2][8][2];

    int stage = 0;

    #pragma unroll 1
    for (int kc = 0; kc < NITER; kc++) {
        CP_WAIT(2);
        __syncthreads();

        // Issue next stage's loads; ALWAYS commit a group (possibly empty) so the
        // wait_group accounting covers the consumed stage even in the tail.
        if (kc + 3 < NITER) {
            int s3 = stage + 3; if (s3 >= NSTAGE) s3 -= NSTAGE;
            issue_stage(s3, kc + 3);
        }
        CP_COMMIT();

        // MODE 1: warm L2 with this CTA's mask tile (128 rows x 512 B) during the
        // last few chunks. 1 prefetch per thread per chunk = 512 lines over 4 chunks.
        if (MODE == 1 && kc >= NITER - 6 && kc < NITER - 2) {
            const int p = kc - (NITER - 6);  // 0..3
            const char* pf = (const char*)(mask + (size_t)(m0 + tid) * ldc + n0) + p * 128;
            asm volatile("prefetch.global.L2 [%0];" :: "l"(pf));
        }

        const uint32_t so = (uint32_t)(stage * STAGE_BYTES);
        const uint32_t a_base = a_warp + so;
        const uint32_t b_base = b_warp + so;

        // load fragments for kstep 0 into buf 0
        #pragma unroll
        for (int mi = 0; mi < 4; mi++)
            ldsm_x4(afr[0][mi], a_base + (uint32_t)(mi * 16 * ROW_BYTES));
        #pragma unroll
        for (int nj = 0; nj < 4; nj++) {
            uint32_t t[4];
            ldsm_x4(t, b_base + (uint32_t)(nj * 16 * ROW_BYTES));
            bfr[0][nj * 2 + 0][0] = t[0]; bfr[0][nj * 2 + 0][1] = t[1];
            bfr[0][nj * 2 + 1][0] = t[2]; bfr[0][nj * 2 + 1][1] = t[3];
        }

        #pragma unroll
        for (int ks = 0; ks < 2; ks++) {
            // prefetch next kstep's fragments into the other buffer
            if (ks == 0) {
                #pragma unroll
                for (int mi = 0; mi < 4; mi++)
                    ldsm_x4(afr[1][mi], a_base + (uint32_t)(mi * 16 * ROW_BYTES + 32));
                #pragma unroll
                for (int nj = 0; nj < 4; nj++) {
                    uint32_t t[4];
                    ldsm_x4(t, b_base + (uint32_t)(nj * 16 * ROW_BYTES + 32));
                    bfr[1][nj * 2 + 0][0] = t[0]; bfr[1][nj * 2 + 0][1] = t[1];
                    bfr[1][nj * 2 + 1][0] = t[2]; bfr[1][nj * 2 + 1][1] = t[3];
                }
            }
            #pragma unroll
            for (int mi = 0; mi < 4; mi++)
                #pragma unroll
                for (int ni = 0; ni < 8; ni++)
                    mma_f16(acc[mi][ni], afr[ks][mi], bfr[ks][ni]);
        }

        if (++stage >= NSTAGE) stage = 0;
    }

    // ---- epilogue ----
    const int lr = lane >> 2;
    const int lc = lane & 3;
    #pragma unroll
    for (int mi = 0; mi < 4; mi++) {
        #pragma unroll
        for (int half_ = 0; half_ < 2; half_++) {
            const int row = m0 + wm + mi * 16 + lr + half_ * 8;
            const int* mrow = (MODE == 1) ? (mask + (size_t)row * ldc) : nullptr;
            #pragma unroll
            for (int ni = 0; ni < 8; ni++) {
                const int col = n0 + wn + ni * 8 + lc * 2;
                float v0 = acc[mi][ni][half_ * 2 + 0];
                float v1 = acc[mi][ni][half_ * 2 + 1];
                if (MODE == 0) {
                    v0 += bias[col];
                    v1 += bias[col + 1];
                }
                if (MODE == 1) {
                    v0 *= scale; v1 *= scale;
                    const int2 mk = *(const int2*)(mrow + col);
                    if (mk.x == 0) v0 = 1e-10f;
                    if (mk.y == 0) v1 = 1e-10f;
                }
                if (OUTH) {
                    __half* C = (__half*)Cv + (long)bz * sC + (size_t)row * ldc + col;
                    *(__half2*)C = __floats2half2_rn(v0, v1);
                } else {
                    float* C = (float*)Cv + (long)bz * sC + (size_t)row * ldc + col;
                    float2 v; v.x = v0; v.y = v1;
                    *(float2*)C = v;
                }
            }
        }
    }
}

// =========================== convert x: fp32 -> half ===========================
__global__ __launch_bounds__(256) void convert_kernel(
    const float* __restrict__ src, __half* __restrict__ dst, size_t n4)
{
    size_t i = (size_t)blockIdx.x * 256 + threadIdx.x;
    if (i >= n4) return;
    float4 v = ((const float4*)src)[i];
    ((__half2*)dst)[i * 2]     = __floats2half2_rn(v.x, v.y);
    ((__half2*)dst)[i * 2 + 1] = __floats2half2_rn(v.z, v.w);
}

// =========================== transpose fp32 -> half ===========================
__global__ __launch_bounds__(256) void transpose_f2h(
    const float* __restrict__ src, __half* __restrict__ dst,
    int srcLd, int dstLd)
{
    __shared__ float t[32][33];
    const int c0 = blockIdx.x * 32, r0 = blockIdx.y * 32;
    const int tx = threadIdx.x, ty = threadIdx.y;
    #pragma unroll
    for (int i = 0; i < 32; i += 8)
        t[ty + i][tx] = src[(size_t)(r0 + ty + i) * srcLd + c0 + tx];
    __syncthreads();
    #pragma unroll
    for (int i = 0; i < 32; i += 8)
        dst[(size_t)(c0 + ty + i) * dstLd + r0 + tx] = __float2half(t[tx][ty + i]);
}

// =========================== transpose half -> half ===========================
__global__ __launch_bounds__(256) void transpose_h2h(
    const __half* __restrict__ src, __half* __restrict__ dst,
    int srcLd, int dstLd, long sBatch, long dBatch)
{
    __shared__ __half t[32][34];
    src += (long)blockIdx.z * sBatch;
    dst += (long)blockIdx.z * dBatch;
    const int c0 = blockIdx.x * 32, r0 = blockIdx.y * 32;
    const int tx = threadIdx.x, ty = threadIdx.y;
    #pragma unroll
    for (int i = 0; i < 32; i += 8)
        t[ty + i][tx] = src[(size_t)(r0 + ty + i) * srcLd + c0 + tx];
    __syncthreads();
    #pragma unroll
    for (int i = 0; i < 32; i += 8)
        dst[(size_t)(c0 + ty + i) * dstLd + r0 + tx] = t[tx][ty + i];
}

// =========== softmax: fp32 scores -> half probs (vectorized, fast exp) ===========
__global__ __launch_bounds__(256) void softmax_kernel(
    const float* __restrict__ s, __half* __restrict__ o)
{
    const long row = blockIdx.x;
    const float4* p4 = (const float4*)(s + row * SEQ);
    __half2* o2 = (__half2*)(o + row * SEQ);
    const int tid  = threadIdx.x;
    const int lane = tid & 31;
    const int warp = tid >> 5;

    __shared__ float redm[8];
    __shared__ float reds[8];

    // 256 threads x 2 float4 = 2048 floats
    float4 v0 = p4[tid];
    float4 v1 = p4[tid + 256];

    float m = fmaxf(fmaxf(fmaxf(v0.x, v0.y), fmaxf(v0.z, v0.w)),
                    fmaxf(fmaxf(v1.x, v1.y), fmaxf(v1.z, v1.w)));
    #pragma unroll
    for (int oo = 16; oo > 0; oo >>= 1) m = fmaxf(m, __shfl_xor_sync(0xffffffffu, m, oo));
    if (lane == 0) redm[warp] = m;
    __syncthreads();
    float M = redm[0];
    #pragma unroll
    for (int i = 1; i < 8; i++) M = fmaxf(M, redm[i]);

    v0.x = __expf(v0.x - M); v0.y = __expf(v0.y - M);
    v0.z = __expf(v0.z - M); v0.w = __expf(v0.w - M);
    v1.x = __expf(v1.x - M); v1.y = __expf(v1.y - M);
    v1.z = __expf(v1.z - M); v1.w = __expf(v1.w - M);

    float sum = (v0.x + v0.y) + (v0.z + v0.w) + (v1.x + v1.y) + (v1.z + v1.w);
    #pragma unroll
    for (int oo = 16; oo > 0; oo >>= 1) sum += __shfl_xor_sync(0xffffffffu, sum, oo);
    if (lane == 0) reds[warp] = sum;
    __syncthreads();
    float total = 0.f;
    #pragma unroll
    for (int i = 0; i < 8; i++) total += reds[i];

    const float inv = 1.0f / total;
    o2[tid * 2 + 0]       = __floats2half2_rn(v0.x * inv, v0.y * inv);
    o2[tid * 2 + 1]       = __floats2half2_rn(v0.z * inv, v0.w * inv);
    o2[512 + tid * 2 + 0] = __floats2half2_rn(v1.x * inv, v1.y * inv);
    o2[512 + tid * 2 + 1] = __floats2half2_rn(v1.z * inv, v1.w * inv);
}

// =========================== launch ===========================
extern "C" void kernel_launch(void* const* d_in, const int* in_sizes, int n_in,
                              void* d_out, int out_size)
{
    const float* x    = (const float*)d_in[0];
    const int*   mask = (const int*)  d_in[1];
    const float* Wqkv = (const float*)d_in[2];
    const float* bqkv = (const float*)d_in[3];
    const float* Wout = (const float*)d_in[4];
    const float* bout = (const float*)d_in[5];
    float* out = (float*)d_out;

    __half* x16;   cudaGetSymbolAddress((void**)&x16,   g_x16);
    __half* qkv;   cudaGetSymbolAddress((void**)&qkv,   g_qkv);
    float*  scores;cudaGetSymbolAddress((void**)&scores,g_scores);
    __half* probs; cudaGetSymbolAddress((void**)&probs, g_probs);
    __half* attn;  cudaGetSymbolAddress((void**)&attn,  g_attn);
    __half* wqkvT; cudaGetSymbolAddress((void**)&wqkvT, g_wqkvT);
    __half* woutT; cudaGetSymbolAddress((void**)&woutT, g_woutT);
    __half* vT;    cudaGetSymbolAddress((void**)&vT,    g_vT);

    cudaFuncSetAttribute(gemm_f16k<0, true>,  cudaFuncAttributeMaxDynamicSharedMemorySize, SMEM_BYTES);
    cudaFuncSetAttribute(gemm_f16k<0, false>, cudaFuncAttributeMaxDynamicSharedMemorySize, SMEM_BYTES);
    cudaFuncSetAttribute(gemm_f16k<1, false>, cudaFuncAttributeMaxDynamicSharedMemorySize, SMEM_BYTES);
    cudaFuncSetAttribute(gemm_f16k<2, true>,  cudaFuncAttributeMaxDynamicSharedMemorySize, SMEM_BYTES);

    // side streams + events (created once, on the uncaptured correctness call;
    // every call issues the IDENTICAL work DAG)
    static cudaStream_t s1 = nullptr, s2 = nullptr;
    static cudaEvent_t  e_begin = nullptr, e_wqkv = nullptr, e_wout = nullptr,
                        e_qkv = nullptr, e_vT = nullptr;
    if (!s1) {
        cudaStreamCreateWithFlags(&s1, cudaStreamNonBlocking);
        cudaStreamCreateWithFlags(&s2, cudaStreamNonBlocking);
        cudaEventCreateWithFlags(&e_begin, cudaEventDisableTiming);
        cudaEventCreateWithFlags(&e_wqkv,  cudaEventDisableTiming);
        cudaEventCreateWithFlags(&e_wout,  cudaEventDisableTiming);
        cudaEventCreateWithFlags(&e_qkv,   cudaEventDisableTiming);
        cudaEventCreateWithFlags(&e_vT,    cudaEventDisableTiming);
    }

    const float scale = 0.03125f;  // 1/sqrt(1024)
    const int M = BATCH * SEQ;     // 8192

    // ---- fork: prologue conversions run concurrently ----
    cudaEventRecord(e_begin, 0);
    cudaStreamWaitEvent(s1, e_begin, 0);
    cudaStreamWaitEvent(s2, e_begin, 0);

    // s0: x -> half
    {
        size_t n4 = (size_t)M * DIM / 4;
        convert_kernel<<<(unsigned)((n4 + 255) / 256), 256>>>(x, x16, n4);
    }
    // s1: Wqkv transpose+convert
    transpose_f2h<<<dim3(3 * DIM / 32, DIM / 32, 1), dim3(32, 8), 0, s1>>>(
        Wqkv, wqkvT, 3 * DIM, DIM);
    cudaEventRecord(e_wqkv, s1);
    // s2: Wout transpose+convert (needed only by step 5)
    transpose_f2h<<<dim3(DIM / 32, DIM / 32, 1), dim3(32, 8), 0, s2>>>(
        Wout, woutT, DIM, DIM);
    cudaEventRecord(e_wout, s2);

    // 1) qkv = x @ Wqkv + bqkv  (half out) — needs x16 (s0) + wqkvT (e_wqkv)
    cudaStreamWaitEvent(0, e_wqkv, 0);
    gemm_f16k<0, true><<<dim3(3 * DIM / BN, M / BM, 1), 128, SMEM_BYTES>>>(
        x16, DIM, wqkvT, DIM, qkv, 3 * DIM, DIM,
        bqkv, nullptr, 0.f, 0, 0, 0, 0);
    cudaEventRecord(e_qkv, 0);

    // s1: V transpose per batch, concurrent with the scores GEMM + softmax
    cudaStreamWaitEvent(s1, e_qkv, 0);
    transpose_h2h<<<dim3(DIM / 32, SEQ / 32, BATCH), dim3(32, 8), 0, s1>>>(
        qkv + 2 * DIM, vT, 3 * DIM, SEQ, (long)SEQ * 3 * DIM, (long)DIM * SEQ);
    cudaEventRecord(e_vT, s1);

    // 2) scores = Q @ K^T * scale, mask==0 -> 1e-10  (fp32 out)
    gemm_f16k<1, false><<<dim3(SEQ / BN, SEQ / BM, BATCH), 128, SMEM_BYTES>>>(
        qkv, 3 * DIM, qkv + DIM, 3 * DIM, scores, SEQ, DIM,
        nullptr, mask, scale,
        (long)SEQ * 3 * DIM, (long)SEQ * 3 * DIM, (long)SEQ * SEQ, (long)SEQ * SEQ);

    // 3) softmax -> half probs
    softmax_kernel<<<BATCH * SEQ, 256>>>(scores, probs);

    // 4) attn_out = probs @ V  (half out) — needs probs (s0) + vT (e_vT)
    cudaStreamWaitEvent(0, e_vT, 0);
    gemm_f16k<2, true><<<dim3(DIM / BN, SEQ / BM, BATCH), 128, SMEM_BYTES>>>(
        probs, SEQ, vT, SEQ, attn, DIM, SEQ,
        nullptr, nullptr, 0.f,
        (long)SEQ * SEQ, (long)DIM * SEQ, (long)SEQ * DIM, 0);

    // 5) out = attn_out @ Wout + bout  (fp32 out) — needs attn (s0) + woutT (e_wout)
    cudaStreamWaitEvent(0, e_wout, 0);
    gemm_f16k<0, false><<<dim3(DIM / BN, M / BM, 1), 128, SMEM_BYTES>>>(
        attn, DIM, woutT, DIM, out, DIM, DIM,
        bout, nullptr, 0.f, 0, 0, 0, 0);
}

// round 17
// speedup vs baseline: 1.1108x; 1.1108x over previous
#include <cuda_runtime.h>
#include <cuda_fp16.h>
#include <cstdint>

#define BATCH 4
#define SEQ   2048
#define DIM   1024

// ---- scratch (alloc-free rule: __device__ globals) ----
__device__ __half g_x16  [(size_t)BATCH * SEQ * DIM];       // x -> half
__device__ __half g_qkv  [(size_t)BATCH * SEQ * 3 * DIM];   // [8192][3072] half
__device__ float  g_scores[(size_t)BATCH * SEQ * SEQ];      // [4][2048][2048] fp32
__device__ __half g_probs[(size_t)BATCH * SEQ * SEQ];       // softmax(scores) half
__device__ __half g_attn [(size_t)BATCH * SEQ * DIM];       // [8192][1024] half
__device__ __half g_wqkvT[(size_t)3 * DIM * DIM];           // [3072][1024] half
__device__ __half g_woutT[(size_t)DIM * DIM];               // [1024][1024] half
__device__ __half g_vT   [(size_t)BATCH * DIM * SEQ];       // [4][1024][2048] half

// =========================== PTX helpers ===========================
__device__ __forceinline__ void mma_f16(float* d, const uint32_t* a, const uint32_t* b) {
    asm volatile(
        "mma.sync.aligned.m16n8k16.row.col.f32.f16.f16.f32 "
        "{%0,%1,%2,%3}, {%4,%5,%6,%7}, {%8,%9}, {%0,%1,%2,%3};"
        : "+f"(d[0]), "+f"(d[1]), "+f"(d[2]), "+f"(d[3])
        : "r"(a[0]), "r"(a[1]), "r"(a[2]), "r"(a[3]), "r"(b[0]), "r"(b[1]));
}

__device__ __forceinline__ void ldsm_x4(uint32_t* r, uint32_t addr) {
    asm volatile("ldmatrix.sync.aligned.m8n8.x4.shared.b16 {%0,%1,%2,%3}, [%4];"
        : "=r"(r[0]), "=r"(r[1]), "=r"(r[2]), "=r"(r[3]) : "r"(addr));
}

__device__ __forceinline__ uint32_t smem_u32(const void* p) {
    uint32_t a;
    asm("{ .reg .u64 t; cvta.to.shared.u64 t, %1; cvt.u32.u64 %0, t; }"
        : "=r"(a) : "l"(p));
    return a;
}

#define CP_ASYNC16(dst_u32, src_ptr) \
    asm volatile("cp.async.cg.shared.global [%0], [%1], 16;" \
                 :: "r"(dst_u32), "l"(src_ptr) : "memory")
#define CP_COMMIT() asm volatile("cp.async.commit_group;" ::: "memory")
#define CP_WAIT(n)  asm volatile("cp.async.wait_group %0;" :: "n"(n) : "memory")

// ====== GEMM: 128 threads, CTA 128x128, BK=32, warp 64x64 (2x2), 4-stage, frag double-buffer ====
// (R11/R13/R14 core, measured best.)
// C[M,N] = A[M,K] * B[N,K]^T.  A, B half, K contiguous.
// MODE 0: +bias[n]   MODE 1: *scale then mask==0 -> 1e-10   MODE 2: plain
// OUTH: write C as half; else fp32.
// Race-safety: a cp.async group is committed EVERY mainloop iteration (empty near the
// tail), so wait_group 2 always guarantees the consumed stage has landed.

constexpr int BM = 128, BN = 128, BK = 32;
constexpr int ROW_HALFS = 40;                          // 32 data + 8 pad, 80 B pitch
constexpr int ROW_BYTES = ROW_HALFS * 2;               // 80
constexpr int A_HALFS = BM * ROW_HALFS;                // 5120
constexpr int STAGE_HALFS = 2 * A_HALFS;               // 10240
constexpr int STAGE_BYTES = STAGE_HALFS * 2;           // 20480
constexpr int NSTAGE = 4;
constexpr int SMEM_BYTES = NSTAGE * STAGE_BYTES;       // 81920

template <int MODE, bool OUTH>
__global__ __launch_bounds__(128, 2) void gemm_f16k(
    const __half* __restrict__ A, int lda,
    const __half* __restrict__ B, int ldb,
    void* __restrict__ Cv, int ldc, int K,
    const float* __restrict__ bias,
    const int* __restrict__ mask, float scale,
    long sA, long sB, long sC, long sM)
{
    extern __shared__ __half smem[];
    const uint32_t smem_base = smem_u32(smem);
    const int tid  = threadIdx.x;
    const int lane = tid & 31;
    const int wid  = tid >> 5;      // 0..3
    const int bz   = blockIdx.z;

    A += (long)bz * sA;
    B += (long)bz * sB;
    if (MODE == 1) mask += (long)bz * sM;

    const int m0 = blockIdx.y * BM;
    const int n0 = blockIdx.x * BN;

    const int wm = (wid & 1) * 64;     // 2 warps in m
    const int wn = (wid >> 1) * 64;    // 2 warps in n

    // ldmatrix per-lane byte offsets (layout verified in R6-R14)
    const uint32_t a_lane = (uint32_t)((lane & 15) * ROW_BYTES + (lane >> 4) * 16);
    const uint32_t b_lane = (uint32_t)(((lane & 7) + ((lane >> 4) << 3)) * ROW_BYTES
                                       + ((lane >> 3) & 1) * 16);

    const uint32_t a_warp = smem_base + (uint32_t)(wm * ROW_BYTES) + a_lane;
    const uint32_t b_warp = smem_base + (uint32_t)(A_HALFS * 2 + wn * ROW_BYTES) + b_lane;

    // cp.async coords: 128 threads; row = tid>>2 (0..31, x4 strides of 32), chunk=(tid&3)*16B
    const int lrow = tid >> 2;
    const int lq   = (tid & 3) * 8;    // halfs

    const __half* Aped = A + (size_t)(m0 + lrow) * lda + lq;
    const __half* Bped = B + (size_t)(n0 + lrow) * ldb + lq;
    const uint32_t a_dst0 = smem_base + (uint32_t)(lrow * ROW_BYTES + lq * 2);
    const uint32_t b_dst0 = smem_base + (uint32_t)(A_HALFS * 2 + lrow * ROW_BYTES + lq * 2);

    const int NITER = K / BK;

    auto issue_stage = [&](int stage, int kc) {
        const uint32_t so = (uint32_t)(stage * STAGE_BYTES);
        const int kb = kc * BK;
        #pragma unroll
        for (int i = 0; i < 4; i++)
            CP_ASYNC16(a_dst0 + so + (uint32_t)(i * 32 * ROW_BYTES),
                       Aped + (size_t)(i * 32) * lda + kb);
        #pragma unroll
        for (int i = 0; i < 4; i++)
            CP_ASYNC16(b_dst0 + so + (uint32_t)(i * 32 * ROW_BYTES),
                       Bped + (size_t)(i * 32) * ldb + kb);
    };

    float acc[4][8][4];
    #pragma unroll
    for (int i = 0; i < 4; i++)
        #pragma unroll
        for (int j = 0; j < 8; j++)
            #pragma unroll
            for (int q = 0; q < 4; q++) acc[i][j][q] = 0.f;

    issue_stage(0, 0); CP_COMMIT();
    issue_stage(1, 1); CP_COMMIT();
    issue_stage(2, 2); CP_COMMIT();

    uint32_t afr[2][4][4], bfr[2][8][2];

    int stage = 0;

    #pragma unroll 1
    for (int kc = 0; kc < NITER; kc++) {
        CP_WAIT(2);
        __syncthreads();

        // Issue next stage's loads; ALWAYS commit a group (possibly empty) so the
        // wait_group accounting covers the consumed stage even in the tail.
        if (kc + 3 < NITER) {
            int s3 = stage + 3; if (s3 >= NSTAGE) s3 -= NSTAGE;
            issue_stage(s3, kc + 3);
        }
        CP_COMMIT();

        const uint32_t so = (uint32_t)(stage * STAGE_BYTES);
        const uint32_t a_base = a_warp + so;
        const uint32_t b_base = b_warp + so;

        // load fragments for kstep 0 into buf 0
        #pragma unroll
        for (int mi = 0; mi < 4; mi++)
            ldsm_x4(afr[0][mi], a_base + (uint32_t)(mi * 16 * ROW_BYTES));
        #pragma unroll
        for (int nj = 0; nj < 4; nj++) {
            uint32_t t[4];
            ldsm_x4(t, b_base + (uint32_t)(nj * 16 * ROW_BYTES));
            bfr[0][nj * 2 + 0][0] = t[0]; bfr[0][nj * 2 + 0][1] = t[1];
            bfr[0][nj * 2 + 1][0] = t[2]; bfr[0][nj * 2 + 1][1] = t[3];
        }

        #pragma unroll
        for (int ks = 0; ks < 2; ks++) {
            // prefetch next kstep's fragments into the other buffer
            if (ks == 0) {
                #pragma unroll
                for (int mi = 0; mi < 4; mi++)
                    ldsm_x4(afr[1][mi], a_base + (uint32_t)(mi * 16 * ROW_BYTES + 32));
                #pragma unroll
                for (int nj = 0; nj < 4; nj++) {
                    uint32_t t[4];
                    ldsm_x4(t, b_base + (uint32_t)(nj * 16 * ROW_BYTES + 32));
                    bfr[1][nj * 2 + 0][0] = t[0]; bfr[1][nj * 2 + 0][1] = t[1];
                    bfr[1][nj * 2 + 1][0] = t[2]; bfr[1][nj * 2 + 1][1] = t[3];
                }
            }
            #pragma unroll
            for (int mi = 0; mi < 4; mi++)
                #pragma unroll
                for (int ni = 0; ni < 8; ni++)
                    mma_f16(acc[mi][ni], afr[ks][mi], bfr[ks][ni]);
        }

        if (++stage >= NSTAGE) stage = 0;
    }

    // ---- epilogue ----
    const int lr = lane >> 2;
    const int lc = lane & 3;
    #pragma unroll
    for (int mi = 0; mi < 4; mi++) {
        #pragma unroll
        for (int half_ = 0; half_ < 2; half_++) {
            const int row = m0 + wm + mi * 16 + lr + half_ * 8;
            const int* mrow = (MODE == 1) ? (mask + (size_t)row * ldc) : nullptr;
            #pragma unroll
            for (int ni = 0; ni < 8; ni++) {
                const int col = n0 + wn + ni * 8 + lc * 2;
                float v0 = acc[mi][ni][half_ * 2 + 0];
                float v1 = acc[mi][ni][half_ * 2 + 1];
                if (MODE == 0) {
                    v0 += bias[col];
                    v1 += bias[col + 1];
                }
                if (MODE == 1) {
                    v0 *= scale; v1 *= scale;
                    const int2 mk = *(const int2*)(mrow + col);
                    if (mk.x == 0) v0 = 1e-10f;
                    if (mk.y == 0) v1 = 1e-10f;
                }
                if (OUTH) {
                    __half* C = (__half*)Cv + (long)bz * sC + (size_t)row * ldc + col;
                    *(__half2*)C = __floats2half2_rn(v0, v1);
                } else {
                    float* C = (float*)Cv + (long)bz * sC + (size_t)row * ldc + col;
                    float2 v; v.x = v0; v.y = v1;
                    *(float2*)C = v;
                }
            }
        }
    }
}

// =========================== convert x: fp32 -> half ===========================
__global__ __launch_bounds__(256) void convert_kernel(
    const float* __restrict__ src, __half* __restrict__ dst, size_t n4)
{
    size_t i = (size_t)blockIdx.x * 256 + threadIdx.x;
    if (i >= n4) return;
    float4 v = ((const float4*)src)[i];
    ((__half2*)dst)[i * 2]     = __floats2half2_rn(v.x, v.y);
    ((__half2*)dst)[i * 2 + 1] = __floats2half2_rn(v.z, v.w);
}

// =========================== transpose fp32 -> half ===========================
__global__ __launch_bounds__(256) void transpose_f2h(
    const float* __restrict__ src, __half* __restrict__ dst,
    int srcLd, int dstLd)
{
    __shared__ float t[32][33];
    const int c0 = blockIdx.x * 32, r0 = blockIdx.y * 32;
    const int tx = threadIdx.x, ty = threadIdx.y;
    #pragma unroll
    for (int i = 0; i < 32; i += 8)
        t[ty + i][tx] = src[(size_t)(r0 + ty + i) * srcLd + c0 + tx];
    __syncthreads();
    #pragma unroll
    for (int i = 0; i < 32; i += 8)
        dst[(size_t)(c0 + ty + i) * dstLd + r0 + tx] = __float2half(t[tx][ty + i]);
}

// =========================== transpose half -> half ===========================
__global__ __launch_bounds__(256) void transpose_h2h(
    const __half* __restrict__ src, __half* __restrict__ dst,
    int srcLd, int dstLd, long sBatch, long dBatch)
{
    __shared__ __half t[32][34];
    src += (long)blockIdx.z * sBatch;
    dst += (long)blockIdx.z * dBatch;
    const int c0 = blockIdx.x * 32, r0 = blockIdx.y * 32;
    const int tx = threadIdx.x, ty = threadIdx.y;
    #pragma unroll
    for (int i = 0; i < 32; i += 8)
        t[ty + i][tx] = src[(size_t)(r0 + ty + i) * srcLd + c0 + tx];
    __syncthreads();
    #pragma unroll
    for (int i = 0; i < 32; i += 8)
        dst[(size_t)(c0 + ty + i) * dstLd + r0 + tx] = t[tx][ty + i];
}

// =========== softmax: fp32 scores -> half probs (vectorized, fast exp) ===========
__global__ __launch_bounds__(256) void softmax_kernel(
    const float* __restrict__ s, __half* __restrict__ o)
{
    const long row = blockIdx.x;
    const float4* p4 = (const float4*)(s + row * SEQ);
    __half2* o2 = (__half2*)(o + row * SEQ);
    const int tid  = threadIdx.x;
    const int lane = tid & 31;
    const int warp = tid >> 5;

    __shared__ float redm[8];
    __shared__ float reds[8];

    // 256 threads x 2 float4 = 2048 floats
    float4 v0 = p4[tid];
    float4 v1 = p4[tid + 256];

    float m = fmaxf(fmaxf(fmaxf(v0.x, v0.y), fmaxf(v0.z, v0.w)),
                    fmaxf(fmaxf(v1.x, v1.y), fmaxf(v1.z, v1.w)));
    #pragma unroll
    for (int oo = 16; oo > 0; oo >>= 1) m = fmaxf(m, __shfl_xor_sync(0xffffffffu, m, oo));
    if (lane == 0) redm[warp] = m;
    __syncthreads();
    float M = redm[0];
    #pragma unroll
    for (int i = 1; i < 8; i++) M = fmaxf(M, redm[i]);

    v0.x = __expf(v0.x - M); v0.y = __expf(v0.y - M);
    v0.z = __expf(v0.z - M); v0.w = __expf(v0.w - M);
    v1.x = __expf(v1.x - M); v1.y = __expf(v1.y - M);
    v1.z = __expf(v1.z - M); v1.w = __expf(v1.w - M);

    float sum = (v0.x + v0.y) + (v0.z + v0.w) + (v1.x + v1.y) + (v1.z + v1.w);
    #pragma unroll
    for (int oo = 16; oo > 0; oo >>= 1) sum += __shfl_xor_sync(0xffffffffu, sum, oo);
    if (lane == 0) reds[warp] = sum;
    __syncthreads();
    float total = 0.f;
    #pragma unroll
    for (int i = 0; i < 8; i++) total += reds[i];

    const float inv = 1.0f / total;
    o2[tid * 2 + 0]       = __floats2half2_rn(v0.x * inv, v0.y * inv);
    o2[tid * 2 + 1]       = __floats2half2_rn(v0.z * inv, v0.w * inv);
    o2[512 + tid * 2 + 0] = __floats2half2_rn(v1.x * inv, v1.y * inv);
    o2[512 + tid * 2 + 1] = __floats2half2_rn(v1.z * inv, v1.w * inv);
}

// =========================== launch ===========================
extern "C" void kernel_launch(void* const* d_in, const int* in_sizes, int n_in,
                              void* d_out, int out_size)
{
    const float* x    = (const float*)d_in[0];
    const int*   mask = (const int*)  d_in[1];
    const float* Wqkv = (const float*)d_in[2];
    const float* bqkv = (const float*)d_in[3];
    const float* Wout = (const float*)d_in[4];
    const float* bout = (const float*)d_in[5];
    float* out = (float*)d_out;

    __half* x16;   cudaGetSymbolAddress((void**)&x16,   g_x16);
    __half* qkv;   cudaGetSymbolAddress((void**)&qkv,   g_qkv);
    float*  scores;cudaGetSymbolAddress((void**)&scores,g_scores);
    __half* probs; cudaGetSymbolAddress((void**)&probs, g_probs);
    __half* attn;  cudaGetSymbolAddress((void**)&attn,  g_attn);
    __half* wqkvT; cudaGetSymbolAddress((void**)&wqkvT, g_wqkvT);
    __half* woutT; cudaGetSymbolAddress((void**)&woutT, g_woutT);
    __half* vT;    cudaGetSymbolAddress((void**)&vT,    g_vT);

    cudaFuncSetAttribute(gemm_f16k<0, true>,  cudaFuncAttributeMaxDynamicSharedMemorySize, SMEM_BYTES);
    cudaFuncSetAttribute(gemm_f16k<0, false>, cudaFuncAttributeMaxDynamicSharedMemorySize, SMEM_BYTES);
    cudaFuncSetAttribute(gemm_f16k<1, false>, cudaFuncAttributeMaxDynamicSharedMemorySize, SMEM_BYTES);
    cudaFuncSetAttribute(gemm_f16k<2, true>,  cudaFuncAttributeMaxDynamicSharedMemorySize, SMEM_BYTES);

    // side streams + events (created once, on the uncaptured correctness call;
    // every call issues the IDENTICAL work DAG)
    static cudaStream_t s1 = nullptr, s2 = nullptr;
    static cudaEvent_t  e_begin = nullptr, e_wqkv = nullptr, e_wout = nullptr,
                        e_qkv = nullptr, e_vT = nullptr;
    if (!s1) {
        cudaStreamCreateWithFlags(&s1, cudaStreamNonBlocking);
        cudaStreamCreateWithFlags(&s2, cudaStreamNonBlocking);
        cudaEventCreateWithFlags(&e_begin, cudaEventDisableTiming);
        cudaEventCreateWithFlags(&e_wqkv,  cudaEventDisableTiming);
        cudaEventCreateWithFlags(&e_wout,  cudaEventDisableTiming);
        cudaEventCreateWithFlags(&e_qkv,   cudaEventDisableTiming);
        cudaEventCreateWithFlags(&e_vT,    cudaEventDisableTiming);
    }

    const float scale = 0.03125f;  // 1/sqrt(1024)
    const int M = BATCH * SEQ;     // 8192

    // ---- fork: prologue conversions run concurrently ----
    cudaEventRecord(e_begin, 0);
    cudaStreamWaitEvent(s1, e_begin, 0);
    cudaStreamWaitEvent(s2, e_begin, 0);

    // s0: x -> half
    {
        size_t n4 = (size_t)M * DIM / 4;
        convert_kernel<<<(unsigned)((n4 + 255) / 256), 256>>>(x, x16, n4);
    }
    // s1: Wqkv transpose+convert
    transpose_f2h<<<dim3(3 * DIM / 32, DIM / 32, 1), dim3(32, 8), 0, s1>>>(
        Wqkv, wqkvT, 3 * DIM, DIM);
    cudaEventRecord(e_wqkv, s1);
    // s2: Wout transpose+convert (needed only by step 5)
    transpose_f2h<<<dim3(DIM / 32, DIM / 32, 1), dim3(32, 8), 0, s2>>>(
        Wout, woutT, DIM, DIM);
    cudaEventRecord(e_wout, s2);

    // 1) qkv = x @ Wqkv + bqkv  (half out) — needs x16 (s0) + wqkvT (e_wqkv)
    cudaStreamWaitEvent(0, e_wqkv, 0);
    gemm_f16k<0, true><<<dim3(3 * DIM / BN, M / BM, 1), 128, SMEM_BYTES>>>(
        x16, DIM, wqkvT, DIM, qkv, 3 * DIM, DIM,
        bqkv, nullptr, 0.f, 0, 0, 0, 0);
    cudaEventRecord(e_qkv, 0);

    // s1: V transpose per batch, concurrent with the scores GEMM + softmax
    cudaStreamWaitEvent(s1, e_qkv, 0);
    transpose_h2h<<<dim3(DIM / 32, SEQ / 32, BATCH), dim3(32, 8), 0, s1>>>(
        qkv + 2 * DIM, vT, 3 * DIM, SEQ, (long)SEQ * 3 * DIM, (long)DIM * SEQ);
    cudaEventRecord(e_vT, s1);

    // 2) scores = Q @ K^T * scale, mask==0 -> 1e-10  (fp32 out)
    gemm_f16k<1, false><<<dim3(SEQ / BN, SEQ / BM, BATCH), 128, SMEM_BYTES>>>(
        qkv, 3 * DIM, qkv + DIM, 3 * DIM, scores, SEQ, DIM,
        nullptr, mask, scale,
        (long)SEQ * 3 * DIM, (long)SEQ * 3 * DIM, (long)SEQ * SEQ, (long)SEQ * SEQ);

    // 3) softmax -> half probs
    softmax_kernel<<<BATCH * SEQ, 256>>>(scores, probs);

    // 4) attn_out = probs @ V  (half out) — needs probs (s0) + vT (e_vT)
    cudaStreamWaitEvent(0, e_vT, 0);
    gemm_f16k<2, true><<<dim3(DIM / BN, SEQ / BM, BATCH), 128, SMEM_BYTES>>>(
        probs, SEQ, vT, SEQ, attn, DIM, SEQ,
        nullptr, nullptr, 0.f,
        (long)SEQ * SEQ, (long)DIM * SEQ, (long)SEQ * DIM, 0);

    // 5) out = attn_out @ Wout + bout  (fp32 out) — needs attn (s0) + woutT (e_wout)
    cudaStreamWaitEvent(0, e_wout, 0);
    gemm_f16k<0, false><<<dim3(DIM / BN, M / BM, 1), 128, SMEM_BYTES>>>(
        attn, DIM, woutT, DIM, out, DIM, DIM,
        bout, nullptr, 0.f, 0, 0, 0, 0);
}